// round 16
// baseline (speedup 1.0000x reference)
#include <cuda_runtime.h>
#include <stdint.h>

typedef unsigned long long u64;
#define FULLMASK 0xffffffffu

static constexpr int B      = 2;
static constexpr int CLS    = 4;
static constexpr int NPTS   = 32;
static constexpr int N_OUT  = CLS * NPTS;     // 128
static constexpr int SVOX   = 1 << 21;        // 128^3
static constexpr int SCAP   = 8192;           // sample buffer per (b,c)
static constexpr int CAP    = 16384;          // survivor buffer per (b,c)
static constexpr int RANK   = 40;             // sample order stat (>= NPTS)
static constexpr int TOPK   = 48;             // f32 safety margin width
static constexpr int COLCAP = 256;            // refined collect capacity
static constexpr unsigned GRIDA = 128u * B;   // sample grid size (flat)

// ---------------- static device scratch (no allocations) -----------------
__device__ float    g_samp[B * CLS][SCAP];
__device__ unsigned g_scnt[B * CLS];
__device__ float    g_cut[B * CLS];
__device__ float    g_td[B * CLS];
__device__ unsigned g_shift[B * CLS];
__device__ u64      g_surv[B * CLS][CAP];
__device__ unsigned g_cnt[B * CLS];
__device__ unsigned g_hist2[B * CLS][256];
__device__ unsigned g_ticketA;

// ---------------- FMA-only exp (x <= 0), rel err ~1e-7, no MUFU ----------
__device__ __forceinline__ float fexp(float x) {
    float t = x * 1.4426950408889634f;
    float n = rintf(t);
    float r = fmaf(n, -0.69314718246459960938f, x);
    r       = fmaf(n,  1.90821492233381634e-9f, r);
    float p = 1.3888889e-3f;
    p = fmaf(p, r, 8.3333333e-3f);
    p = fmaf(p, r, 4.1666667e-2f);
    p = fmaf(p, r, 1.6666667e-1f);
    p = fmaf(p, r, 0.5f);
    p = fmaf(p, r, 1.0f);
    p = fmaf(p, r, 1.0f);                      // fexp(0) == 1 exactly
    int e = (int)n;
    e = e < -126 ? -126 : (e > 126 ? 126 : e);
    return p * __int_as_float((e + 127) << 23);
}

// bit-identical in sample and scan slow path (survivor guarantee needs it)
__device__ __forceinline__ float s_of(float a, float b, float c, float d, float m) {
    return fexp(a - m) + fexp(b - m) + fexp(c - m) + fexp(d - m);   // [1,4)
}
__device__ __forceinline__ int argmax4(float a, float b, float c, float d, float& m) {
    m = a; int am = 0;
    if (b > m) { m = b; am = 1; }
    if (c > m) { m = c; am = 2; }
    if (d > m) { m = d; am = 3; }
    return am;
}

// ---- parallel 256-bin histogram crossing (256 threads) ----
__device__ __forceinline__ void hist_cross(const unsigned* hist, unsigned basecum,
                                           unsigned target, unsigned* wsum,
                                           volatile unsigned* sF,
                                           volatile unsigned* sBelow, int tid) {
    unsigned h = hist[tid];
    unsigned lane = tid & 31, wd = (unsigned)tid >> 5;
    unsigned v = h;
    for (int d = 1; d < 32; d <<= 1) {
        unsigned t = __shfl_up_sync(FULLMASK, v, d);
        if (lane >= d) v += t;
    }
    if (lane == 31) wsum[wd] = v;
    __syncthreads();
    unsigned add = basecum;
    for (unsigned j = 0; j < wd; j++) add += wsum[j];
    unsigned incl = v + add;
    unsigned excl = incl - h;
    if (incl >= target && excl < target) {     // unique first-crossing thread
        *sF = (unsigned)tid;
        *sBelow = excl;
    }
    __syncthreads();
}

// ---------------- kernel A: 1/64 sampling + fused last-block cutoff ------
// flat grid GRIDA = 256 blocks, 256 threads; block r: batch r>>7, chunk r&127
__global__ __launch_bounds__(256) void sample_kernel(const float* __restrict__ logits) {
    const int tid = threadIdx.x;
    const int b   = blockIdx.x >> 7;
    unsigned v = (unsigned)(blockIdx.x & 127) * 16384u + (unsigned)tid;
    const float* base = logits + (size_t)b * CLS * SVOX;
    float a  = base[v];
    float x1 = base[SVOX + v];
    float x2 = base[2u * SVOX + v];
    float x3 = base[3u * SVOX + v];
    float m; int am = argmax4(a, x1, x2, x3, m);
    float s = s_of(a, x1, x2, x3, m);
    if (s < 2.0f) {                            // prob_argmax = 1/s > 0.5
        int g = b * CLS + am;
        unsigned p = atomicAdd(&g_scnt[g], 1u);
        if (p < SCAP) g_samp[g][p] = s;
    }

    // ---- last-block-ticket: single finisher computes all 8 cutoffs ----
    __shared__ unsigned sflag;
    __threadfence();
    __syncthreads();
    if (tid == 0) sflag = (atomicAdd(&g_ticketA, 1u) == GRIDA - 1u) ? 1u : 0u;
    __syncthreads();
    if (!sflag) return;
    __threadfence();

    __shared__ unsigned hist8[B * CLS][256];   // 8 KB, one row per group
    for (int i = tid; i < B * CLS * 256; i += 256) ((unsigned*)hist8)[i] = 0u;
    __syncthreads();

    const int wp = tid >> 5, lane = tid & 31;  // warp wp handles group wp
    {
        const int g = wp;
        unsigned mc = g_scnt[g]; if (mc > SCAP) mc = SCAP;
        float cut = 2.0f;
        if (mc >= (unsigned)RANK) {
            for (unsigned i = lane; i < mc; i += 32) {
                unsigned d = __float_as_uint(g_samp[g][i]) - 0x3F800000u;
                atomicAdd(&hist8[g][d >> 15], 1u);
            }
            __syncwarp();
            // warp-level crossing: lane covers bins [lane*8, lane*8+8)
            unsigned seg = 0;
#pragma unroll
            for (int j = 0; j < 8; j++) seg += hist8[g][lane * 8 + j];
            unsigned incl = seg;
            for (int d = 1; d < 32; d <<= 1) {
                unsigned t = __shfl_up_sync(FULLMASK, incl, d);
                if (lane >= d) incl += t;
            }
            unsigned excl = incl - seg;
            int Fbin = -1;
            if (incl >= (unsigned)RANK && excl < (unsigned)RANK) {
                unsigned cum = excl;
#pragma unroll
                for (int j = 0; j < 8; j++) {
                    cum += hist8[g][lane * 8 + j];
                    if (cum >= (unsigned)RANK) { Fbin = lane * 8 + j; break; }
                }
            }
            for (int o = 16; o; o >>= 1) {     // broadcast the one valid Fbin
                int t = __shfl_xor_sync(FULLMASK, Fbin, o);
                if (t > Fbin) Fbin = t;
            }
            cut = __uint_as_float(0x3F800000u + ((unsigned)(Fbin + 1) << 15));
        }
        if (lane == 0) {
            g_cut[g] = cut;
            g_td[g]  = -logf(cut - 1.0f) - 0.01f;   // gap > td necessary for s < cut
            unsigned edge = __float_as_uint(cut) - 0x3F800000u;
            unsigned sh = 0;
            while ((edge >> sh) > 256u) sh++;
            g_shift[g] = sh;
            g_cnt[g]  = 0u;                    // ready for scan
            g_scnt[g] = 0u;                    // ready for next replay
        }
    }
    __syncthreads();
    for (int i = tid; i < B * CLS * 256; i += 256) ((unsigned*)g_hist2)[i] = 0u;
    __syncthreads();
    if (tid == 0) g_ticketA = 0u;              // ready for next replay
}

// ---------------- kernel B: exp-free full scan + survivor histogram ------
// grid = B*(SVOX/2048) = 2048 blocks, 256 threads, 8 voxels/thread
__global__ __launch_bounds__(256) void scan_kernel(const float* __restrict__ logits) {
    const int tid = threadIdx.x;
    const int b   = blockIdx.x >> 10;
    const unsigned v0 = (unsigned)(blockIdx.x & 1023) * 2048u + (unsigned)tid * 8u;

    const float td = fminf(fminf(g_td[b * CLS],     g_td[b * CLS + 1]),
                           fminf(g_td[b * CLS + 2], g_td[b * CLS + 3]));

    const float4* p4 = (const float4*)(logits + (size_t)b * CLS * SVOX);
    float c0[8], c1[8], c2[8], c3[8];
    {
        float4 u, w;
        u = p4[(0u * SVOX + v0) >> 2]; w = p4[((0u * SVOX + v0) >> 2) + 1];
        c0[0]=u.x; c0[1]=u.y; c0[2]=u.z; c0[3]=u.w; c0[4]=w.x; c0[5]=w.y; c0[6]=w.z; c0[7]=w.w;
        u = p4[(1u * SVOX + v0) >> 2]; w = p4[((1u * SVOX + v0) >> 2) + 1];
        c1[0]=u.x; c1[1]=u.y; c1[2]=u.z; c1[3]=u.w; c1[4]=w.x; c1[5]=w.y; c1[6]=w.z; c1[7]=w.w;
        u = p4[(2u * SVOX + v0) >> 2]; w = p4[((2u * SVOX + v0) >> 2) + 1];
        c2[0]=u.x; c2[1]=u.y; c2[2]=u.z; c2[3]=u.w; c2[4]=w.x; c2[5]=w.y; c2[6]=w.z; c2[7]=w.w;
        u = p4[(3u * SVOX + v0) >> 2]; w = p4[((3u * SVOX + v0) >> 2) + 1];
        c3[0]=u.x; c3[1]=u.y; c3[2]=u.z; c3[3]=u.w; c3[4]=w.x; c3[5]=w.y; c3[6]=w.z; c3[7]=w.w;
    }

    // cheap necessary screen: hi - sec <= |max(pair1) - max(pair2)|
    unsigned mask = 0u;
#pragma unroll
    for (int i = 0; i < 8; i++) {
        float m1 = fmaxf(c0[i], c1[i]);
        float m2 = fmaxf(c2[i], c3[i]);
        if (fabsf(m1 - m2) >= td) mask |= 1u << i;
    }

    if (__any_sync(FULLMASK, mask != 0u)) {    // warp-uniform rare branch
#pragma unroll
        for (int i = 0; i < 8; i++) {
            if (mask & (1u << i)) {
                float a = c0[i], bb = c1[i], cc = c2[i], dd = c3[i];
                float m; int am = argmax4(a, bb, cc, dd, m);
                float s = s_of(a, bb, cc, dd, m);
                int g = b * CLS + am;
                if (s < g_cut[g]) {
                    unsigned d = __float_as_uint(s) - 0x3F800000u;
                    u64 key = ((u64)__float_as_uint(s) << 21) | (u64)(v0 + (unsigned)i);
                    unsigned pos = atomicAdd(&g_cnt[g], 1u);
                    if (pos < (unsigned)CAP) g_surv[g][pos] = key;
                    atomicAdd(&g_hist2[g][d >> g_shift[g]], 1u);
                }
            }
        }
    }
}

// ---------------- double-precision exact key for final ranking -----------
__device__ __forceinline__ u64 dkey(u64 fkey, const float* __restrict__ base) {
    if (fkey == ~0ull) return ~0ull;
    unsigned idx = (unsigned)(fkey & 0x1FFFFFu);
    double a  = (double)base[idx];
    double x1 = (double)base[SVOX + idx];
    double x2 = (double)base[2u * SVOX + idx];
    double x3 = (double)base[3u * SVOX + idx];
    double m  = fmax(fmax(a, x1), fmax(x2, x3));
    double sd = exp(a - m) + exp(x1 - m) + exp(x2 - m) + exp(x3 - m);
    u64 diff = (u64)__double_as_longlong(sd) - 0x3FF0000000000000ull;
    if (diff > 0xFFFFFFFFFFFFFull) diff = 0xFFFFFFFFFFFFFull;
    return ((diff >> 9) << 21) | (u64)idx;     // asc = best; tie -> smaller idx
}

// ---------------- kernel C: hist-driven collect + rank-select + output ---
// grid = B*CLS blocks, 256 threads
__global__ __launch_bounds__(256) void final_kernel(const float* __restrict__ logits,
                                                    float* __restrict__ out,
                                                    int out_size) {
    __shared__ unsigned hist[256];
    __shared__ unsigned wsum[8];
    __shared__ unsigned sF, sBelow;
    __shared__ u64 coll[COLCAP];
    __shared__ u64 ek[COLCAP];
    __shared__ unsigned s_nc;
    __shared__ u64 s_top[TOPK];
    __shared__ u64 red8[8];
    __shared__ u64 bc;

    const int g = blockIdx.x, tid = threadIdx.x;
    const int b = g >> 2, c = g & 3;
    const int w = (c + 3) & 3;                 // position in visit order [1,2,3,0]
    float* crd = out;                           // coords [B][128][3]
    const bool has_lab = out_size >= B * N_OUT * 4;
    float* lab = out + (out_size - B * N_OUT); // labels [B][128] at tail

    int cnt = (int)g_cnt[g];
    int m = cnt > CAP ? CAP : cnt;
    int k = cnt < NPTS ? cnt : NPTS; if (k > m) k = m;
    int off = 0;
    for (int o = 0; o < w; o++) {
        int t = (int)g_cnt[b * CLS + ((o + 1) & 3)];
        off += t < NPTS ? t : NPTS;
    }
    if (w == 3) {                              // last class fills padding tail
        int tot = off + k;
        for (int i = tot + tid; i < N_OUT; i += 256) {
            if (has_lab) lab[b * N_OUT + i] = -1.0f;
            crd[(b * N_OUT + i) * 3 + 0] = 0.0f;
            crd[(b * N_OUT + i) * 3 + 1] = 0.0f;
            crd[(b * N_OUT + i) * 3 + 2] = 0.0f;
        }
    }

    const unsigned target = (unsigned)(cnt < TOPK ? cnt : TOPK);
    const int shift = (int)g_shift[g];

    hist[tid] = g_hist2[g][tid];               // global survivor histogram
    if (tid == 0) { s_nc = 0u; sF = 255u; sBelow = 0u; }
    __syncthreads();
    hist_cross(hist, 0u, target, wsum, &sF, &sBelow, tid);
    const int F = (int)sF;
    const unsigned nc1 = sBelow + hist[F];

    const float* base = logits + (size_t)b * CLS * SVOX;

    if (cnt <= CAP && nc1 <= (unsigned)COLCAP) {
        // ---- common path: one collect sweep over survivors ----
        for (int i = tid; i < m; i += 256) {
            u64 key = g_surv[g][i];
            unsigned d = (unsigned)((key >> 21) - 0x3F800000u);
            if ((int)(d >> shift) <= F)
                coll[atomicAdd(&s_nc, 1u)] = key;
        }
        __syncthreads();
        const unsigned nc = s_nc;

        // parallel exact keys (one double-exp chain per thread)
        ek[tid] = (tid < (int)nc) ? dkey(coll[tid], base) : ~0ull;
        __syncthreads();

        // O(n^2) rank selection (keys unique), fully parallel output
        if (tid < (int)nc) {
            u64 mine = ek[tid];
            int rank = 0;
            for (int j = 0; j < (int)nc; j++) rank += (ek[j] < mine);
            if (rank < k) {
                int idx  = (int)(mine & 0x1FFFFFull);
                int slot = off + rank;
                if (has_lab) lab[b * N_OUT + slot] = (float)c;
                crd[(b * N_OUT + slot) * 3 + 0] = (float)(idx >> 14);
                crd[(b * N_OUT + slot) * 3 + 1] = (float)((idx >> 7) & 127);
                crd[(b * N_OUT + slot) * 3 + 2] = (float)(idx & 127);
            }
        }
    } else {
        // ---- fallback (cnt>CAP or massive ties): serial extraction ----
        u64 prev = 0; int found = 0;
        for (int r = 0; r < TOPK; r++) {
            u64 loc = ~0ull;
            for (int i = tid; i < m; i += 256) {
                u64 kk = g_surv[g][i];
                if (kk > prev && kk < loc) loc = kk;
            }
            for (int o = 16; o; o >>= 1) {
                u64 t = __shfl_xor_sync(FULLMASK, loc, o);
                if (t < loc) loc = t;
            }
            if ((tid & 31) == 0) red8[tid >> 5] = loc;
            __syncthreads();
            if (tid == 0) {
                u64 mn = red8[0];
                for (int j = 1; j < 8; j++) if (red8[j] < mn) mn = red8[j];
                bc = mn; s_top[r] = mn;
            }
            __syncthreads();
            prev = bc;
            __syncthreads();
            if (prev == ~0ull) break;
            found = r + 1;
        }
        if (tid == 0)
            for (int r = found; r < TOPK; r++) s_top[r] = ~0ull;
        __syncthreads();

        if (tid < 32) {
            u64 k0 = dkey(s_top[tid], base);
            u64 k1 = (tid < 16) ? dkey(s_top[32 + tid], base) : ~0ull;
            for (int r = 0; r < k; r++) {
                u64 mn = k0 < k1 ? k0 : k1;
                for (int o = 16; o; o >>= 1) {
                    u64 t = __shfl_xor_sync(FULLMASK, mn, o);
                    if (t < mn) mn = t;
                }
                if (mn == ~0ull) break;
                if (k0 == mn) k0 = ~0ull; else if (k1 == mn) k1 = ~0ull;
                if (tid == 0) {
                    int idx  = (int)(mn & 0x1FFFFFull);
                    int slot = off + r;
                    if (has_lab) lab[b * N_OUT + slot] = (float)c;
                    crd[(b * N_OUT + slot) * 3 + 0] = (float)(idx >> 14);
                    crd[(b * N_OUT + slot) * 3 + 1] = (float)((idx >> 7) & 127);
                    crd[(b * N_OUT + slot) * 3 + 2] = (float)(idx & 127);
                }
            }
        }
    }
}

// ---------------- launch (kernel launches ONLY) ---------------------------
extern "C" void kernel_launch(void* const* d_in, const int* in_sizes, int n_in,
                              void* d_out, int out_size) {
    const long long want = (long long)B * CLS * SVOX;   // 16,777,216
    int li = 0;
    for (int i = 0; i < n_in; i++)
        if ((long long)in_sizes[i] == want) { li = i; break; }
    if ((long long)in_sizes[li] != want)
        for (int i = 1; i < n_in; i++)
            if (in_sizes[i] > in_sizes[li]) li = i;

    const float* logits = (const float*)d_in[li];
    float* out = (float*)d_out;

    sample_kernel<<<GRIDA, 256>>>(logits);
    scan_kernel<<<B * (SVOX / 2048), 256>>>(logits);
    final_kernel<<<B * CLS, 256>>>(logits, out, out_size);
}